// round 9
// baseline (speedup 1.0000x reference)
#include <cuda_runtime.h>

// Problem constants (fixed by the dataset)
#define NN 50000
#define DD 64
#define EE 1250000

// Scratch (device globals). 16B-aligned for vector ld/st.
__device__ __align__(16) float g_dis[NN];        // weighted deg -> deg^{-1/2}
__device__ __align__(16) float g_h[NN * DD];     // post-GEMM features
__device__ __align__(16) float g_agg[NN * DD];   // aggregation buffer
__device__ __align__(16) int   g_deg[NN];        // in-degree counts
__device__ __align__(16) int   g_off[NN + 1];    // CSR offsets
__device__ __align__(16) int   g_cur[NN];        // placement cursors
__device__ __align__(16) int   g_src[EE];        // CSR source node per slot
__device__ __align__(16) float g_enorm[EE];      // CSR edge norm per slot

// ---------------------------------------------------------------------------
__global__ void init_k() {
    int i = blockIdx.x * blockDim.x + threadIdx.x;
    if (i < NN) {
        g_dis[i] = 2.0f;  // improved=True self-loop weight seeds the degree
        g_deg[i] = 0;
    }
}

// 2 edges per thread, vectorized index/weight loads
__global__ void count_k(const int* __restrict__ cols,
                        const float* __restrict__ w) {
    int t = blockIdx.x * blockDim.x + threadIdx.x;
    int e = t * 2;
    if (e + 1 < EE) {
        int2 c2 = *(const int2*)(cols + e);
        float2 w2 = *(const float2*)(w + e);
        if ((unsigned)c2.x < NN) { atomicAdd(&g_deg[c2.x], 1); atomicAdd(&g_dis[c2.x], w2.x); }
        if ((unsigned)c2.y < NN) { atomicAdd(&g_deg[c2.y], 1); atomicAdd(&g_dis[c2.y], w2.y); }
    } else if (e < EE) {
        unsigned c = (unsigned)cols[e];
        if (c < NN) { atomicAdd(&g_deg[c], 1); atomicAdd(&g_dis[c], w[e]); }
    }
}

// Single-block scan of g_deg -> g_off/g_cur; also finalizes dis = deg^{-1/2}.
__global__ void scan_k() {
    __shared__ int partial[1024];
    const int CH = (NN + 1023) / 1024;  // 49
    int t = threadIdx.x;
    int base = t * CH;
    int sum = 0;
    for (int i = 0; i < CH; i++) {
        int idx = base + i;
        if (idx < NN) sum += g_deg[idx];
    }
    partial[t] = sum;
    __syncthreads();
    for (int off = 1; off < 1024; off <<= 1) {
        int v = (t >= off) ? partial[t - off] : 0;
        __syncthreads();
        partial[t] += v;
        __syncthreads();
    }
    int run = (t > 0) ? partial[t - 1] : 0;
    for (int i = 0; i < CH; i++) {
        int idx = base + i;
        if (idx < NN) {
            g_off[idx] = run;
            g_cur[idx] = run;
            run += g_deg[idx];
            float d = g_dis[idx];
            g_dis[idx] = (d > 0.0f) ? rsqrtf(d) : 0.0f;  // fused rsqrt pass
        }
    }
    if (t == 1023) g_off[NN] = partial[1023];
}

__global__ void fill_k(const int* __restrict__ rows,
                       const int* __restrict__ cols,
                       const float* __restrict__ w) {
    int t = blockIdx.x * blockDim.x + threadIdx.x;
    int e = t * 2;
#pragma unroll
    for (int q = 0; q < 2; q++, e++) {
        if (e < EE) {
            unsigned r = (unsigned)rows[e];
            unsigned c = (unsigned)cols[e];
            if (r < NN && c < NN) {
                int pos = atomicAdd(&g_cur[c], 1);
                g_src[pos] = (int)r;
                g_enorm[pos] = g_dis[r] * w[e] * g_dis[c];
            }
        }
    }
}

// ---------------------------------------------------------------------------
// GEMM: g_h[32-row tile] = act(X) @ W, act = (bias? relu(x+bias) : x)
// 128 threads; each thread computes a 4x4 micro-tile. X==nullptr -> read g_agg.
// (R7-proven configuration.)
// ---------------------------------------------------------------------------
__global__ __launch_bounds__(128) void gemm_k(const float* __restrict__ X,
                                              const float* __restrict__ W,
                                              const float* __restrict__ bias) {
    __shared__ float Ws[64][65];
    __shared__ float Xs[32][65];
    int tx = threadIdx.x;
    int row0 = blockIdx.x * 32;
    const float* __restrict__ src = X ? X : (const float*)g_agg;

    for (int i = tx; i < 64 * 16; i += 128) {
        int k = i >> 4, c4 = (i & 15) * 4;
        float4 v = *(const float4*)(W + k * 64 + c4);
        Ws[k][c4] = v.x; Ws[k][c4 + 1] = v.y; Ws[k][c4 + 2] = v.z; Ws[k][c4 + 3] = v.w;
    }
    for (int i = tx; i < 32 * 16; i += 128) {
        int r = i >> 4, c4 = (i & 15) * 4;
        int gr = row0 + r;
        float4 v = make_float4(0.f, 0.f, 0.f, 0.f);
        if (gr < NN) v = *(const float4*)(src + (size_t)gr * 64 + c4);
        if (bias) {
            v.x = fmaxf(v.x + bias[c4], 0.f);
            v.y = fmaxf(v.y + bias[c4 + 1], 0.f);
            v.z = fmaxf(v.z + bias[c4 + 2], 0.f);
            v.w = fmaxf(v.w + bias[c4 + 3], 0.f);
        }
        Xs[r][c4] = v.x; Xs[r][c4 + 1] = v.y; Xs[r][c4 + 2] = v.z; Xs[r][c4 + 3] = v.w;
    }
    __syncthreads();

    int rB = (tx >> 4) * 4;   // 0..28
    int cB = (tx & 15) * 4;   // 0..60
    float acc[4][4] = {};
#pragma unroll
    for (int k = 0; k < 64; k++) {
        float xv[4], wv[4];
#pragma unroll
        for (int i = 0; i < 4; i++) xv[i] = Xs[rB + i][k];
#pragma unroll
        for (int j = 0; j < 4; j++) wv[j] = Ws[k][cB + j];
#pragma unroll
        for (int i = 0; i < 4; i++)
#pragma unroll
            for (int j = 0; j < 4; j++) acc[i][j] = fmaf(xv[i], wv[j], acc[i][j]);
    }
#pragma unroll
    for (int i = 0; i < 4; i++) {
        int gr = row0 + rB + i;
        if (gr < NN) {
            float4 v = make_float4(acc[i][0], acc[i][1], acc[i][2], acc[i][3]);
            *(float4*)(g_h + (size_t)gr * 64 + cB) = v;
        }
    }
}

// ---------------------------------------------------------------------------
// Gather core (R7 form + unroll-4): warp per node, float2 per lane,
// 4 independent 256B row reads in flight per iteration.
// ---------------------------------------------------------------------------
__device__ __forceinline__ float2 gather_row(int node, int lane) {
    int beg = g_off[node];
    int end = g_off[node + 1];
    float s = g_dis[node];
    float self = 2.0f * s * s;
    float2 h0 = *(const float2*)(g_h + (size_t)node * 64 + lane * 2);
    float ax = h0.x * self, ay = h0.y * self;

    int j = beg;
    for (; j + 3 < end; j += 4) {
        int s0 = g_src[j], s1 = g_src[j + 1], s2 = g_src[j + 2], s3 = g_src[j + 3];
        float w0 = g_enorm[j], w1 = g_enorm[j + 1], w2 = g_enorm[j + 2], w3 = g_enorm[j + 3];
        float2 v0 = *(const float2*)(g_h + (size_t)s0 * 64 + lane * 2);
        float2 v1 = *(const float2*)(g_h + (size_t)s1 * 64 + lane * 2);
        float2 v2 = *(const float2*)(g_h + (size_t)s2 * 64 + lane * 2);
        float2 v3 = *(const float2*)(g_h + (size_t)s3 * 64 + lane * 2);
        ax = fmaf(w0, v0.x, ax); ay = fmaf(w0, v0.y, ay);
        ax = fmaf(w1, v1.x, ax); ay = fmaf(w1, v1.y, ay);
        ax = fmaf(w2, v2.x, ax); ay = fmaf(w2, v2.y, ay);
        ax = fmaf(w3, v3.x, ax); ay = fmaf(w3, v3.y, ay);
    }
    for (; j < end; j++) {
        int s0 = g_src[j];
        float w0 = g_enorm[j];
        float2 v0 = *(const float2*)(g_h + (size_t)s0 * 64 + lane * 2);
        ax = fmaf(w0, v0.x, ax); ay = fmaf(w0, v0.y, ay);
    }
    return make_float2(ax, ay);
}

__global__ __launch_bounds__(256) void gather_k() {
    int warp = (blockIdx.x * blockDim.x + threadIdx.x) >> 5;
    int lane = threadIdx.x & 31;
    if (warp >= NN) return;
    float2 acc = gather_row(warp, lane);
    *(float2*)(g_agg + (size_t)warp * 64 + lane * 2) = acc;
}

// Last layer: gather fused with relu(agg+b).Wf + bf -> out
__global__ __launch_bounds__(256) void gather_final_k(const float* __restrict__ bias,
                                                      const float* __restrict__ Wf,
                                                      const float* __restrict__ bf,
                                                      float* __restrict__ out) {
    int warp = (blockIdx.x * blockDim.x + threadIdx.x) >> 5;
    int lane = threadIdx.x & 31;
    if (warp >= NN) return;
    float2 acc = gather_row(warp, lane);
    float s = fmaxf(acc.x + bias[lane * 2], 0.f) * Wf[lane * 2]
            + fmaxf(acc.y + bias[lane * 2 + 1], 0.f) * Wf[lane * 2 + 1];
#pragma unroll
    for (int o = 16; o; o >>= 1) s += __shfl_xor_sync(0xFFFFFFFFu, s, o);
    if (lane == 0) out[warp] = s + bf[0];
}

// ---------------------------------------------------------------------------
extern "C" void kernel_launch(void* const* d_in, const int* in_sizes, int n_in,
                              void* d_out, int out_size) {
    const float* x   = (const float*)d_in[0];
    const int*   ei  = (const int*)d_in[1];    // [2, E] int32
    const float* ew  = (const float*)d_in[2];
    const float* Ws  = (const float*)d_in[3];  // [3, 64, 64]
    const float* bs  = (const float*)d_in[4];  // [3, 64]
    const float* Wf  = (const float*)d_in[5];  // [64, 1]
    const float* bf  = (const float*)d_in[6];
    float*       out = (float*)d_out;

    const int* rows = ei;        // source nodes
    const int* cols = ei + EE;   // target nodes

    const int TB = 256;
    const int gemm_blocks = (NN + 31) / 32;
    const int node_warp_blocks = (NN * 32 + TB - 1) / TB;
    const int edge2_blocks = (EE / 2 + TB - 1) / TB;

    // --- CSR build + gcn_norm (once; reused across layers) ---
    init_k<<<(NN + TB - 1) / TB, TB>>>();
    count_k<<<edge2_blocks, TB>>>(cols, ew);
    scan_k<<<1, 1024>>>();                      // offsets + rsqrt fused
    fill_k<<<edge2_blocks, TB>>>(rows, cols, ew);

    // --- layer 0 ---
    gemm_k<<<gemm_blocks, 128>>>(x, Ws, nullptr);
    gather_k<<<node_warp_blocks, TB>>>();

    // --- layer 1 (bias0+relu fused into GEMM read of g_agg) ---
    gemm_k<<<gemm_blocks, 128>>>(nullptr, Ws + 64 * 64, bs);
    gather_k<<<node_warp_blocks, TB>>>();

    // --- layer 2 + final projection fused into the gather ---
    gemm_k<<<gemm_blocks, 128>>>(nullptr, Ws + 2 * 64 * 64, bs + 64);
    gather_final_k<<<node_warp_blocks, TB>>>(bs + 128, Wf, bf, out);
}

// round 11
// speedup vs baseline: 1.0143x; 1.0143x over previous
#include <cuda_runtime.h>

// Problem constants (fixed by the dataset)
#define NN 50000
#define DD 64
#define EE 1250000

// Scratch (device globals). 16B-aligned for vector ld/st.
__device__ __align__(16) float g_dis[NN];        // weighted deg -> deg^{-1/2}
__device__ __align__(16) float g_h[NN * DD];     // post-GEMM features
__device__ __align__(16) float g_agg[NN * DD];   // aggregation buffer
__device__ __align__(16) int   g_deg[NN];        // in-degree counts
__device__ __align__(16) int   g_off[NN + 1];    // CSR offsets
__device__ __align__(16) int   g_cur[NN];        // placement cursors
__device__ __align__(16) int   g_src[EE];        // CSR source node per slot
__device__ __align__(16) float g_enorm[EE];      // CSR edge norm per slot

// ---------------------------------------------------------------------------
__global__ void init_k() {
    int i = blockIdx.x * blockDim.x + threadIdx.x;
    if (i < NN) {
        g_dis[i] = 2.0f;  // improved=True self-loop weight seeds the degree
        g_deg[i] = 0;
    }
}

// R7 form: 1 edge per thread (max parallelism hides atomic latency best)
__global__ void count_k(const int* __restrict__ cols,
                        const float* __restrict__ w) {
    int e = blockIdx.x * blockDim.x + threadIdx.x;
    if (e < EE) {
        unsigned c = (unsigned)cols[e];
        if (c < NN) {
            atomicAdd(&g_deg[c], 1);
            atomicAdd(&g_dis[c], w[e]);
        }
    }
}

// Single-block scan of g_deg -> g_off/g_cur; finalizes dis = deg^{-1/2}.
// Chunk loads via int4 (4x fewer transactions on the uncoalesced pattern).
__global__ void scan_k() {
    __shared__ int partial[1024];
    const int CH = 52;                       // 52*1024 >= 50000, 52 % 4 == 0
    int t = threadIdx.x;
    int base = t * CH;
    int sum = 0;
    for (int i = 0; i < CH; i += 4) {
        int idx = base + i;
        if (idx + 3 < NN) {
            int4 v = *(const int4*)(g_deg + idx);
            sum += v.x + v.y + v.z + v.w;
        } else {
            for (int q = 0; q < 4; q++)
                if (idx + q < NN) sum += g_deg[idx + q];
        }
    }
    partial[t] = sum;
    __syncthreads();
    for (int off = 1; off < 1024; off <<= 1) {
        int v = (t >= off) ? partial[t - off] : 0;
        __syncthreads();
        partial[t] += v;
        __syncthreads();
    }
    int run = (t > 0) ? partial[t - 1] : 0;
    for (int i = 0; i < CH; i++) {
        int idx = base + i;
        if (idx < NN) {
            g_off[idx] = run;
            g_cur[idx] = run;
            run += g_deg[idx];
            float d = g_dis[idx];
            g_dis[idx] = (d > 0.0f) ? rsqrtf(d) : 0.0f;  // fused rsqrt pass
        }
    }
    if (t == 1023) g_off[NN] = partial[1023];
}

// R7 form: 1 edge per thread
__global__ void fill_k(const int* __restrict__ rows,
                       const int* __restrict__ cols,
                       const float* __restrict__ w) {
    int e = blockIdx.x * blockDim.x + threadIdx.x;
    if (e < EE) {
        unsigned r = (unsigned)rows[e];
        unsigned c = (unsigned)cols[e];
        if (r < NN && c < NN) {
            int pos = atomicAdd(&g_cur[c], 1);
            g_src[pos] = (int)r;
            g_enorm[pos] = g_dis[r] * w[e] * g_dis[c];
        }
    }
}

// ---------------------------------------------------------------------------
// GEMM (R7-proven): g_h[32-row tile] = act(X) @ W, 128 threads, 4x4 micro-tile.
// X==nullptr -> read g_agg.
// ---------------------------------------------------------------------------
__global__ __launch_bounds__(128) void gemm_k(const float* __restrict__ X,
                                              const float* __restrict__ W,
                                              const float* __restrict__ bias) {
    __shared__ float Ws[64][65];
    __shared__ float Xs[32][65];
    int tx = threadIdx.x;
    int row0 = blockIdx.x * 32;
    const float* __restrict__ src = X ? X : (const float*)g_agg;

    for (int i = tx; i < 64 * 16; i += 128) {
        int k = i >> 4, c4 = (i & 15) * 4;
        float4 v = *(const float4*)(W + k * 64 + c4);
        Ws[k][c4] = v.x; Ws[k][c4 + 1] = v.y; Ws[k][c4 + 2] = v.z; Ws[k][c4 + 3] = v.w;
    }
    for (int i = tx; i < 32 * 16; i += 128) {
        int r = i >> 4, c4 = (i & 15) * 4;
        int gr = row0 + r;
        float4 v = make_float4(0.f, 0.f, 0.f, 0.f);
        if (gr < NN) v = *(const float4*)(src + (size_t)gr * 64 + c4);
        if (bias) {
            v.x = fmaxf(v.x + bias[c4], 0.f);
            v.y = fmaxf(v.y + bias[c4 + 1], 0.f);
            v.z = fmaxf(v.z + bias[c4 + 2], 0.f);
            v.w = fmaxf(v.w + bias[c4 + 3], 0.f);
        }
        Xs[r][c4] = v.x; Xs[r][c4 + 1] = v.y; Xs[r][c4 + 2] = v.z; Xs[r][c4 + 3] = v.w;
    }
    __syncthreads();

    int rB = (tx >> 4) * 4;   // 0..28
    int cB = (tx & 15) * 4;   // 0..60
    float acc[4][4] = {};
#pragma unroll
    for (int k = 0; k < 64; k++) {
        float xv[4], wv[4];
#pragma unroll
        for (int i = 0; i < 4; i++) xv[i] = Xs[rB + i][k];
#pragma unroll
        for (int j = 0; j < 4; j++) wv[j] = Ws[k][cB + j];
#pragma unroll
        for (int i = 0; i < 4; i++)
#pragma unroll
            for (int j = 0; j < 4; j++) acc[i][j] = fmaf(xv[i], wv[j], acc[i][j]);
    }
#pragma unroll
    for (int i = 0; i < 4; i++) {
        int gr = row0 + rB + i;
        if (gr < NN) {
            float4 v = make_float4(acc[i][0], acc[i][1], acc[i][2], acc[i][3]);
            *(float4*)(g_h + (size_t)gr * 64 + cB) = v;
        }
    }
}

// ---------------------------------------------------------------------------
// Gather (R7-proven): warp per node, float2 per lane, unroll-2.
// ---------------------------------------------------------------------------
__device__ __forceinline__ float2 gather_row(int node, int lane) {
    int beg = g_off[node];
    int end = g_off[node + 1];
    float s = g_dis[node];
    float self = 2.0f * s * s;
    float2 h0 = *(const float2*)(g_h + (size_t)node * 64 + lane * 2);
    float ax = h0.x * self, ay = h0.y * self;

    int j = beg;
    for (; j + 1 < end; j += 2) {
        int s0 = g_src[j], s1 = g_src[j + 1];
        float w0 = g_enorm[j], w1 = g_enorm[j + 1];
        float2 v0 = *(const float2*)(g_h + (size_t)s0 * 64 + lane * 2);
        float2 v1 = *(const float2*)(g_h + (size_t)s1 * 64 + lane * 2);
        ax = fmaf(w0, v0.x, ax); ay = fmaf(w0, v0.y, ay);
        ax = fmaf(w1, v1.x, ax); ay = fmaf(w1, v1.y, ay);
    }
    if (j < end) {
        int s0 = g_src[j];
        float w0 = g_enorm[j];
        float2 v0 = *(const float2*)(g_h + (size_t)s0 * 64 + lane * 2);
        ax = fmaf(w0, v0.x, ax); ay = fmaf(w0, v0.y, ay);
    }
    return make_float2(ax, ay);
}

__global__ __launch_bounds__(256) void gather_k() {
    int warp = (blockIdx.x * blockDim.x + threadIdx.x) >> 5;
    int lane = threadIdx.x & 31;
    if (warp >= NN) return;
    float2 acc = gather_row(warp, lane);
    *(float2*)(g_agg + (size_t)warp * 64 + lane * 2) = acc;
}

// Last layer: gather fused with relu(agg+b).Wf + bf -> out
__global__ __launch_bounds__(256) void gather_final_k(const float* __restrict__ bias,
                                                      const float* __restrict__ Wf,
                                                      const float* __restrict__ bf,
                                                      float* __restrict__ out) {
    int warp = (blockIdx.x * blockDim.x + threadIdx.x) >> 5;
    int lane = threadIdx.x & 31;
    if (warp >= NN) return;
    float2 acc = gather_row(warp, lane);
    float s = fmaxf(acc.x + bias[lane * 2], 0.f) * Wf[lane * 2]
            + fmaxf(acc.y + bias[lane * 2 + 1], 0.f) * Wf[lane * 2 + 1];
#pragma unroll
    for (int o = 16; o; o >>= 1) s += __shfl_xor_sync(0xFFFFFFFFu, s, o);
    if (lane == 0) out[warp] = s + bf[0];
}

// ---------------------------------------------------------------------------
extern "C" void kernel_launch(void* const* d_in, const int* in_sizes, int n_in,
                              void* d_out, int out_size) {
    const float* x   = (const float*)d_in[0];
    const int*   ei  = (const int*)d_in[1];    // [2, E] int32
    const float* ew  = (const float*)d_in[2];
    const float* Ws  = (const float*)d_in[3];  // [3, 64, 64]
    const float* bs  = (const float*)d_in[4];  // [3, 64]
    const float* Wf  = (const float*)d_in[5];  // [64, 1]
    const float* bf  = (const float*)d_in[6];
    float*       out = (float*)d_out;

    const int* rows = ei;        // source nodes
    const int* cols = ei + EE;   // target nodes

    const int TB = 256;
    const int gemm_blocks = (NN + 31) / 32;
    const int node_warp_blocks = (NN * 32 + TB - 1) / TB;
    const int edge_blocks = (EE + TB - 1) / TB;

    // --- CSR build + gcn_norm (once; reused across layers) ---
    init_k<<<(NN + TB - 1) / TB, TB>>>();
    count_k<<<edge_blocks, TB>>>(cols, ew);
    scan_k<<<1, 1024>>>();                      // offsets + rsqrt fused
    fill_k<<<edge_blocks, TB>>>(rows, cols, ew);

    // --- layer 0 ---
    gemm_k<<<gemm_blocks, 128>>>(x, Ws, nullptr);
    gather_k<<<node_warp_blocks, TB>>>();

    // --- layer 1 (bias0+relu fused into GEMM read of g_agg) ---
    gemm_k<<<gemm_blocks, 128>>>(nullptr, Ws + 64 * 64, bs);
    gather_k<<<node_warp_blocks, TB>>>();

    // --- layer 2 + final projection fused into the gather ---
    gemm_k<<<gemm_blocks, 128>>>(nullptr, Ws + 2 * 64 * 64, bs + 64);
    gather_final_k<<<node_warp_blocks, TB>>>(bs + 128, Wf, bf, out);
}

// round 13
// speedup vs baseline: 1.1740x; 1.1575x over previous
#include <cuda_runtime.h>

// Problem constants (fixed by the dataset)
#define NN 50000
#define DD 64
#define EE 1250000

// Scratch (device globals). 16B-aligned for vector ld/st.
__device__ __align__(16) float g_dis[NN];        // weighted deg -> deg^{-1/2}
__device__ __align__(16) float g_h[NN * DD];     // post-GEMM features
__device__ __align__(16) float g_agg[NN * DD];   // aggregation buffer
__device__ __align__(16) int   g_deg[NN];        // in-degree counts
__device__ __align__(16) int   g_off[NN + 1];    // CSR offsets
__device__ __align__(16) int   g_cur[NN];        // placement cursors
__device__ __align__(16) int2  g_edge[EE];       // CSR packed {src, norm bits}

// ---------------------------------------------------------------------------
__global__ void init_k() {
    int i = blockIdx.x * blockDim.x + threadIdx.x;
    if (i < NN) {
        g_dis[i] = 2.0f;  // improved=True self-loop weight seeds the degree
        g_deg[i] = 0;
    }
}

// 1 edge per thread (max parallelism hides atomic latency best)
__global__ void count_k(const int* __restrict__ cols,
                        const float* __restrict__ w) {
    int e = blockIdx.x * blockDim.x + threadIdx.x;
    if (e < EE) {
        unsigned c = (unsigned)cols[e];
        if (c < NN) {
            atomicAdd(&g_deg[c], 1);
            atomicAdd(&g_dis[c], w[e]);
        }
    }
}

// Single-block exclusive scan of g_deg -> g_off/g_cur. (R7 exact: no extra work.)
__global__ void scan_k() {
    __shared__ int partial[1024];
    const int CH = (NN + 1023) / 1024;  // 49
    int t = threadIdx.x;
    int base = t * CH;
    int sum = 0;
    for (int i = 0; i < CH; i++) {
        int idx = base + i;
        if (idx < NN) sum += g_deg[idx];
    }
    partial[t] = sum;
    __syncthreads();
    for (int off = 1; off < 1024; off <<= 1) {
        int v = (t >= off) ? partial[t - off] : 0;
        __syncthreads();
        partial[t] += v;
        __syncthreads();
    }
    int run = (t > 0) ? partial[t - 1] : 0;
    for (int i = 0; i < CH; i++) {
        int idx = base + i;
        if (idx < NN) {
            g_off[idx] = run;
            g_cur[idx] = run;
            run += g_deg[idx];
        }
    }
    if (t == 1023) g_off[NN] = partial[1023];
}

// Parallel rsqrt pass (R7 exact; keep it OUT of the single-block scan)
__global__ void rsqrt_k() {
    int i = blockIdx.x * blockDim.x + threadIdx.x;
    if (i < NN) {
        float d = g_dis[i];
        g_dis[i] = (d > 0.0f) ? rsqrtf(d) : 0.0f;
    }
}

// Fill CSR slots with packed {src, norm} (one 8B store per edge)
__global__ void fill_k(const int* __restrict__ rows,
                       const int* __restrict__ cols,
                       const float* __restrict__ w) {
    int e = blockIdx.x * blockDim.x + threadIdx.x;
    if (e < EE) {
        unsigned r = (unsigned)rows[e];
        unsigned c = (unsigned)cols[e];
        if (r < NN && c < NN) {
            int pos = atomicAdd(&g_cur[c], 1);
            float nrm = g_dis[r] * w[e] * g_dis[c];
            g_edge[pos] = make_int2((int)r, __float_as_int(nrm));
        }
    }
}

// ---------------------------------------------------------------------------
// GEMM (R7-proven): g_h[32-row tile] = act(X) @ W, 128 threads, 4x4 micro-tile.
// X==nullptr -> read g_agg.
// ---------------------------------------------------------------------------
__global__ __launch_bounds__(128) void gemm_k(const float* __restrict__ X,
                                              const float* __restrict__ W,
                                              const float* __restrict__ bias) {
    __shared__ float Ws[64][65];
    __shared__ float Xs[32][65];
    int tx = threadIdx.x;
    int row0 = blockIdx.x * 32;
    const float* __restrict__ src = X ? X : (const float*)g_agg;

    for (int i = tx; i < 64 * 16; i += 128) {
        int k = i >> 4, c4 = (i & 15) * 4;
        float4 v = *(const float4*)(W + k * 64 + c4);
        Ws[k][c4] = v.x; Ws[k][c4 + 1] = v.y; Ws[k][c4 + 2] = v.z; Ws[k][c4 + 3] = v.w;
    }
    for (int i = tx; i < 32 * 16; i += 128) {
        int r = i >> 4, c4 = (i & 15) * 4;
        int gr = row0 + r;
        float4 v = make_float4(0.f, 0.f, 0.f, 0.f);
        if (gr < NN) v = *(const float4*)(src + (size_t)gr * 64 + c4);
        if (bias) {
            v.x = fmaxf(v.x + bias[c4], 0.f);
            v.y = fmaxf(v.y + bias[c4 + 1], 0.f);
            v.z = fmaxf(v.z + bias[c4 + 2], 0.f);
            v.w = fmaxf(v.w + bias[c4 + 3], 0.f);
        }
        Xs[r][c4] = v.x; Xs[r][c4 + 1] = v.y; Xs[r][c4 + 2] = v.z; Xs[r][c4 + 3] = v.w;
    }
    __syncthreads();

    int rB = (tx >> 4) * 4;   // 0..28
    int cB = (tx & 15) * 4;   // 0..60
    float acc[4][4] = {};
#pragma unroll
    for (int k = 0; k < 64; k++) {
        float xv[4], wv[4];
#pragma unroll
        for (int i = 0; i < 4; i++) xv[i] = Xs[rB + i][k];
#pragma unroll
        for (int j = 0; j < 4; j++) wv[j] = Ws[k][cB + j];
#pragma unroll
        for (int i = 0; i < 4; i++)
#pragma unroll
            for (int j = 0; j < 4; j++) acc[i][j] = fmaf(xv[i], wv[j], acc[i][j]);
    }
#pragma unroll
    for (int i = 0; i < 4; i++) {
        int gr = row0 + rB + i;
        if (gr < NN) {
            float4 v = make_float4(acc[i][0], acc[i][1], acc[i][2], acc[i][3]);
            *(float4*)(g_h + (size_t)gr * 64 + cB) = v;
        }
    }
}

// ---------------------------------------------------------------------------
// Gather: warp per node, float2 per lane, unroll-2, packed edge stream.
// ---------------------------------------------------------------------------
__device__ __forceinline__ float2 gather_row(int node, int lane) {
    int beg = g_off[node];
    int end = g_off[node + 1];
    float s = g_dis[node];
    float self = 2.0f * s * s;
    float2 h0 = *(const float2*)(g_h + (size_t)node * 64 + lane * 2);
    float ax = h0.x * self, ay = h0.y * self;

    int j = beg;
    for (; j + 1 < end; j += 2) {
        int2 p0 = g_edge[j];
        int2 p1 = g_edge[j + 1];
        float w0 = __int_as_float(p0.y);
        float w1 = __int_as_float(p1.y);
        float2 v0 = *(const float2*)(g_h + (size_t)p0.x * 64 + lane * 2);
        float2 v1 = *(const float2*)(g_h + (size_t)p1.x * 64 + lane * 2);
        ax = fmaf(w0, v0.x, ax); ay = fmaf(w0, v0.y, ay);
        ax = fmaf(w1, v1.x, ax); ay = fmaf(w1, v1.y, ay);
    }
    if (j < end) {
        int2 p0 = g_edge[j];
        float w0 = __int_as_float(p0.y);
        float2 v0 = *(const float2*)(g_h + (size_t)p0.x * 64 + lane * 2);
        ax = fmaf(w0, v0.x, ax); ay = fmaf(w0, v0.y, ay);
    }
    return make_float2(ax, ay);
}

__global__ __launch_bounds__(256) void gather_k() {
    int warp = (blockIdx.x * blockDim.x + threadIdx.x) >> 5;
    int lane = threadIdx.x & 31;
    if (warp >= NN) return;
    float2 acc = gather_row(warp, lane);
    *(float2*)(g_agg + (size_t)warp * 64 + lane * 2) = acc;
}

// Last layer: gather fused with relu(agg+b).Wf + bf -> out
__global__ __launch_bounds__(256) void gather_final_k(const float* __restrict__ bias,
                                                      const float* __restrict__ Wf,
                                                      const float* __restrict__ bf,
                                                      float* __restrict__ out) {
    int warp = (blockIdx.x * blockDim.x + threadIdx.x) >> 5;
    int lane = threadIdx.x & 31;
    if (warp >= NN) return;
    float2 acc = gather_row(warp, lane);
    float s = fmaxf(acc.x + bias[lane * 2], 0.f) * Wf[lane * 2]
            + fmaxf(acc.y + bias[lane * 2 + 1], 0.f) * Wf[lane * 2 + 1];
#pragma unroll
    for (int o = 16; o; o >>= 1) s += __shfl_xor_sync(0xFFFFFFFFu, s, o);
    if (lane == 0) out[warp] = s + bf[0];
}

// ---------------------------------------------------------------------------
extern "C" void kernel_launch(void* const* d_in, const int* in_sizes, int n_in,
                              void* d_out, int out_size) {
    const float* x   = (const float*)d_in[0];
    const int*   ei  = (const int*)d_in[1];    // [2, E] int32
    const float* ew  = (const float*)d_in[2];
    const float* Ws  = (const float*)d_in[3];  // [3, 64, 64]
    const float* bs  = (const float*)d_in[4];  // [3, 64]
    const float* Wf  = (const float*)d_in[5];  // [64, 1]
    const float* bf  = (const float*)d_in[6];
    float*       out = (float*)d_out;

    const int* rows = ei;        // source nodes
    const int* cols = ei + EE;   // target nodes

    const int TB = 256;
    const int gemm_blocks = (NN + 31) / 32;
    const int node_warp_blocks = (NN * 32 + TB - 1) / TB;
    const int edge_blocks = (EE + TB - 1) / TB;

    // --- CSR build + gcn_norm (once; reused across layers) ---
    init_k<<<(NN + TB - 1) / TB, TB>>>();
    count_k<<<edge_blocks, TB>>>(cols, ew);
    scan_k<<<1, 1024>>>();
    rsqrt_k<<<(NN + TB - 1) / TB, TB>>>();      // parallel, NOT in scan_k
    fill_k<<<edge_blocks, TB>>>(rows, cols, ew);

    // --- layer 0 ---
    gemm_k<<<gemm_blocks, 128>>>(x, Ws, nullptr);
    gather_k<<<node_warp_blocks, TB>>>();

    // --- layer 1 (bias0+relu fused into GEMM read of g_agg) ---
    gemm_k<<<gemm_blocks, 128>>>(nullptr, Ws + 64 * 64, bs);
    gather_k<<<node_warp_blocks, TB>>>();

    // --- layer 2 + final projection fused into the gather ---
    gemm_k<<<gemm_blocks, 128>>>(nullptr, Ws + 2 * 64 * 64, bs + 64);
    gather_final_k<<<node_warp_blocks, TB>>>(bs + 128, Wf, bf, out);
}

// round 14
// speedup vs baseline: 1.2369x; 1.0536x over previous
#include <cuda_runtime.h>
#include <cuda_fp16.h>

// Problem constants (fixed by the dataset)
#define NN 50000
#define DD 64
#define EE 1250000

// Scratch (device globals). 16B-aligned for vector ld/st.
__device__ __align__(16) float  g_dis[NN];        // weighted deg -> deg^{-1/2}
__device__ __align__(16) __half g_h[NN * DD];     // post-GEMM features (fp16!)
__device__ __align__(16) float  g_agg[NN * DD];   // aggregation buffer (fp32)
__device__ __align__(16) int    g_deg[NN];        // in-degree counts
__device__ __align__(16) int    g_off[NN + 1];    // CSR offsets
__device__ __align__(16) int    g_cur[NN];        // placement cursors
__device__ __align__(16) int2   g_edge[EE];       // CSR packed {src, norm bits}

// ---------------------------------------------------------------------------
__global__ void init_k() {
    int i = blockIdx.x * blockDim.x + threadIdx.x;
    if (i < NN) {
        g_dis[i] = 2.0f;  // improved=True self-loop weight seeds the degree
        g_deg[i] = 0;
    }
}

__global__ void count_k(const int* __restrict__ cols,
                        const float* __restrict__ w) {
    int e = blockIdx.x * blockDim.x + threadIdx.x;
    if (e < EE) {
        unsigned c = (unsigned)cols[e];
        if (c < NN) {
            atomicAdd(&g_deg[c], 1);
            atomicAdd(&g_dis[c], w[e]);
        }
    }
}

// Single-block exclusive scan of g_deg -> g_off/g_cur (no extra work in here!)
__global__ void scan_k() {
    __shared__ int partial[1024];
    const int CH = (NN + 1023) / 1024;  // 49
    int t = threadIdx.x;
    int base = t * CH;
    int sum = 0;
    for (int i = 0; i < CH; i++) {
        int idx = base + i;
        if (idx < NN) sum += g_deg[idx];
    }
    partial[t] = sum;
    __syncthreads();
    for (int off = 1; off < 1024; off <<= 1) {
        int v = (t >= off) ? partial[t - off] : 0;
        __syncthreads();
        partial[t] += v;
        __syncthreads();
    }
    int run = (t > 0) ? partial[t - 1] : 0;
    for (int i = 0; i < CH; i++) {
        int idx = base + i;
        if (idx < NN) {
            g_off[idx] = run;
            g_cur[idx] = run;
            run += g_deg[idx];
        }
    }
    if (t == 1023) g_off[NN] = partial[1023];
}

// Parallel rsqrt pass (kept OUT of the single-block scan)
__global__ void rsqrt_k() {
    int i = blockIdx.x * blockDim.x + threadIdx.x;
    if (i < NN) {
        float d = g_dis[i];
        g_dis[i] = (d > 0.0f) ? rsqrtf(d) : 0.0f;
    }
}

// Fill CSR slots with packed {src, norm} (one 8B store per edge)
__global__ void fill_k(const int* __restrict__ rows,
                       const int* __restrict__ cols,
                       const float* __restrict__ w) {
    int e = blockIdx.x * blockDim.x + threadIdx.x;
    if (e < EE) {
        unsigned r = (unsigned)rows[e];
        unsigned c = (unsigned)cols[e];
        if (r < NN && c < NN) {
            int pos = atomicAdd(&g_cur[c], 1);
            float nrm = g_dis[r] * w[e] * g_dis[c];
            g_edge[pos] = make_int2((int)r, __float_as_int(nrm));
        }
    }
}

// ---------------------------------------------------------------------------
// GEMM: g_h[32-row tile] = act(X) @ W (fp32 math, fp16 output store).
// 128 threads, 4x4 micro-tile. X==nullptr -> read g_agg.
// ---------------------------------------------------------------------------
__global__ __launch_bounds__(128) void gemm_k(const float* __restrict__ X,
                                              const float* __restrict__ W,
                                              const float* __restrict__ bias) {
    __shared__ float Ws[64][65];
    __shared__ float Xs[32][65];
    int tx = threadIdx.x;
    int row0 = blockIdx.x * 32;
    const float* __restrict__ src = X ? X : (const float*)g_agg;

    for (int i = tx; i < 64 * 16; i += 128) {
        int k = i >> 4, c4 = (i & 15) * 4;
        float4 v = *(const float4*)(W + k * 64 + c4);
        Ws[k][c4] = v.x; Ws[k][c4 + 1] = v.y; Ws[k][c4 + 2] = v.z; Ws[k][c4 + 3] = v.w;
    }
    for (int i = tx; i < 32 * 16; i += 128) {
        int r = i >> 4, c4 = (i & 15) * 4;
        int gr = row0 + r;
        float4 v = make_float4(0.f, 0.f, 0.f, 0.f);
        if (gr < NN) v = *(const float4*)(src + (size_t)gr * 64 + c4);
        if (bias) {
            v.x = fmaxf(v.x + bias[c4], 0.f);
            v.y = fmaxf(v.y + bias[c4 + 1], 0.f);
            v.z = fmaxf(v.z + bias[c4 + 2], 0.f);
            v.w = fmaxf(v.w + bias[c4 + 3], 0.f);
        }
        Xs[r][c4] = v.x; Xs[r][c4 + 1] = v.y; Xs[r][c4 + 2] = v.z; Xs[r][c4 + 3] = v.w;
    }
    __syncthreads();

    int rB = (tx >> 4) * 4;   // 0..28
    int cB = (tx & 15) * 4;   // 0..60
    float acc[4][4] = {};
#pragma unroll
    for (int k = 0; k < 64; k++) {
        float xv[4], wv[4];
#pragma unroll
        for (int i = 0; i < 4; i++) xv[i] = Xs[rB + i][k];
#pragma unroll
        for (int j = 0; j < 4; j++) wv[j] = Ws[k][cB + j];
#pragma unroll
        for (int i = 0; i < 4; i++)
#pragma unroll
            for (int j = 0; j < 4; j++) acc[i][j] = fmaf(xv[i], wv[j], acc[i][j]);
    }
#pragma unroll
    for (int i = 0; i < 4; i++) {
        int gr = row0 + rB + i;
        if (gr < NN) {
            __half2 h01 = __floats2half2_rn(acc[i][0], acc[i][1]);
            __half2 h23 = __floats2half2_rn(acc[i][2], acc[i][3]);
            uint2 pv;
            pv.x = *reinterpret_cast<unsigned*>(&h01);
            pv.y = *reinterpret_cast<unsigned*>(&h23);
            *(uint2*)(g_h + (size_t)gr * 64 + cB) = pv;
        }
    }
}

// ---------------------------------------------------------------------------
// Gather: warp per node, 2 dims per lane (one half2 load = 4B/lane, 128B/warp),
// unroll-2, packed edge stream. Accumulation in fp32.
// ---------------------------------------------------------------------------
__device__ __forceinline__ float2 gather_row(int node, int lane) {
    int beg = g_off[node];
    int end = g_off[node + 1];
    float s = g_dis[node];
    float self = 2.0f * s * s;
    float2 h0 = __half22float2(*(const __half2*)(g_h + (size_t)node * 64 + lane * 2));
    float ax = h0.x * self, ay = h0.y * self;

    int j = beg;
    for (; j + 1 < end; j += 2) {
        int2 p0 = g_edge[j];
        int2 p1 = g_edge[j + 1];
        float w0 = __int_as_float(p0.y);
        float w1 = __int_as_float(p1.y);
        float2 v0 = __half22float2(*(const __half2*)(g_h + (size_t)p0.x * 64 + lane * 2));
        float2 v1 = __half22float2(*(const __half2*)(g_h + (size_t)p1.x * 64 + lane * 2));
        ax = fmaf(w0, v0.x, ax); ay = fmaf(w0, v0.y, ay);
        ax = fmaf(w1, v1.x, ax); ay = fmaf(w1, v1.y, ay);
    }
    if (j < end) {
        int2 p0 = g_edge[j];
        float w0 = __int_as_float(p0.y);
        float2 v0 = __half22float2(*(const __half2*)(g_h + (size_t)p0.x * 64 + lane * 2));
        ax = fmaf(w0, v0.x, ax); ay = fmaf(w0, v0.y, ay);
    }
    return make_float2(ax, ay);
}

__global__ __launch_bounds__(256) void gather_k() {
    int warp = (blockIdx.x * blockDim.x + threadIdx.x) >> 5;
    int lane = threadIdx.x & 31;
    if (warp >= NN) return;
    float2 acc = gather_row(warp, lane);
    *(float2*)(g_agg + (size_t)warp * 64 + lane * 2) = acc;
}

// Last layer: gather fused with relu(agg+b).Wf + bf -> out
__global__ __launch_bounds__(256) void gather_final_k(const float* __restrict__ bias,
                                                      const float* __restrict__ Wf,
                                                      const float* __restrict__ bf,
                                                      float* __restrict__ out) {
    int warp = (blockIdx.x * blockDim.x + threadIdx.x) >> 5;
    int lane = threadIdx.x & 31;
    if (warp >= NN) return;
    float2 acc = gather_row(warp, lane);
    float s = fmaxf(acc.x + bias[lane * 2], 0.f) * Wf[lane * 2]
            + fmaxf(acc.y + bias[lane * 2 + 1], 0.f) * Wf[lane * 2 + 1];
#pragma unroll
    for (int o = 16; o; o >>= 1) s += __shfl_xor_sync(0xFFFFFFFFu, s, o);
    if (lane == 0) out[warp] = s + bf[0];
}

// ---------------------------------------------------------------------------
extern "C" void kernel_launch(void* const* d_in, const int* in_sizes, int n_in,
                              void* d_out, int out_size) {
    const float* x   = (const float*)d_in[0];
    const int*   ei  = (const int*)d_in[1];    // [2, E] int32
    const float* ew  = (const float*)d_in[2];
    const float* Ws  = (const float*)d_in[3];  // [3, 64, 64]
    const float* bs  = (const float*)d_in[4];  // [3, 64]
    const float* Wf  = (const float*)d_in[5];  // [64, 1]
    const float* bf  = (const float*)d_in[6];
    float*       out = (float*)d_out;

    const int* rows = ei;        // source nodes
    const int* cols = ei + EE;   // target nodes

    const int TB = 256;
    const int gemm_blocks = (NN + 31) / 32;
    const int node_warp_blocks = (NN * 32 + TB - 1) / TB;
    const int edge_blocks = (EE + TB - 1) / TB;

    // --- CSR build + gcn_norm (once; reused across layers) ---
    init_k<<<(NN + TB - 1) / TB, TB>>>();
    count_k<<<edge_blocks, TB>>>(cols, ew);
    scan_k<<<1, 1024>>>();
    rsqrt_k<<<(NN + TB - 1) / TB, TB>>>();
    fill_k<<<edge_blocks, TB>>>(rows, cols, ew);

    // --- layer 0 ---
    gemm_k<<<gemm_blocks, 128>>>(x, Ws, nullptr);
    gather_k<<<node_warp_blocks, TB>>>();

    // --- layer 1 (bias0+relu fused into GEMM read of g_agg) ---
    gemm_k<<<gemm_blocks, 128>>>(nullptr, Ws + 64 * 64, bs);
    gather_k<<<node_warp_blocks, TB>>>();

    // --- layer 2 + final projection fused into the gather ---
    gemm_k<<<gemm_blocks, 128>>>(nullptr, Ws + 2 * 64 * 64, bs + 64);
    gather_final_k<<<node_warp_blocks, TB>>>(bs + 128, Wf, bf, out);
}

// round 16
// speedup vs baseline: 1.2372x; 1.0003x over previous
#include <cuda_runtime.h>
#include <cuda_fp16.h>

// Problem constants (fixed by the dataset)
#define NN 50000
#define DD 64
#define EE 1250000

// Scratch (device globals). 16B-aligned for vector ld/st.
__device__ __align__(16) float  g_dis[NN];        // weighted deg -> deg^{-1/2}
__device__ __align__(16) __half g_h[NN * DD];     // post-GEMM features (fp16)
__device__ __align__(16) float  g_agg[NN * DD];   // aggregation buffer (fp32)
__device__ __align__(16) int    g_deg[NN];        // in-degree counts
__device__ __align__(16) int    g_off[NN + 1];    // CSR offsets
__device__ __align__(16) int    g_cur[NN];        // placement cursors
__device__ __align__(16) int2   g_edge[EE];       // CSR packed {src, norm bits}

// ---------------------------------------------------------------------------
__global__ void init_k() {
    int i = blockIdx.x * blockDim.x + threadIdx.x;
    if (i < NN) {
        g_dis[i] = 2.0f;  // improved=True self-loop weight seeds the degree
        g_deg[i] = 0;
    }
}

__global__ void count_k(const int* __restrict__ cols,
                        const float* __restrict__ w) {
    int e = blockIdx.x * blockDim.x + threadIdx.x;
    if (e < EE) {
        unsigned c = (unsigned)cols[e];
        if (c < NN) {
            atomicAdd(&g_deg[c], 1);
            atomicAdd(&g_dis[c], w[e]);
        }
    }
}

// Single-block exclusive scan of g_deg -> g_off/g_cur (no extra work in here!)
__global__ void scan_k() {
    __shared__ int partial[1024];
    const int CH = (NN + 1023) / 1024;  // 49
    int t = threadIdx.x;
    int base = t * CH;
    int sum = 0;
    for (int i = 0; i < CH; i++) {
        int idx = base + i;
        if (idx < NN) sum += g_deg[idx];
    }
    partial[t] = sum;
    __syncthreads();
    for (int off = 1; off < 1024; off <<= 1) {
        int v = (t >= off) ? partial[t - off] : 0;
        __syncthreads();
        partial[t] += v;
        __syncthreads();
    }
    int run = (t > 0) ? partial[t - 1] : 0;
    for (int i = 0; i < CH; i++) {
        int idx = base + i;
        if (idx < NN) {
            g_off[idx] = run;
            g_cur[idx] = run;
            run += g_deg[idx];
        }
    }
    if (t == 1023) g_off[NN] = partial[1023];
}

// Parallel rsqrt pass (kept OUT of the single-block scan)
__global__ void rsqrt_k() {
    int i = blockIdx.x * blockDim.x + threadIdx.x;
    if (i < NN) {
        float d = g_dis[i];
        g_dis[i] = (d > 0.0f) ? rsqrtf(d) : 0.0f;
    }
}

// Fill CSR slots with packed {src, norm} (one 8B store per edge)
__global__ void fill_k(const int* __restrict__ rows,
                       const int* __restrict__ cols,
                       const float* __restrict__ w) {
    int e = blockIdx.x * blockDim.x + threadIdx.x;
    if (e < EE) {
        unsigned r = (unsigned)rows[e];
        unsigned c = (unsigned)cols[e];
        if (r < NN && c < NN) {
            int pos = atomicAdd(&g_cur[c], 1);
            float nrm = g_dis[r] * w[e] * g_dis[c];
            g_edge[pos] = make_int2((int)r, __float_as_int(nrm));
        }
    }
}

// ---------------------------------------------------------------------------
// GEMM: g_h[32-row tile] = act(X) @ W (fp32 math, fp16 output store).
// 128 threads, 4x4 micro-tile. X==nullptr -> read g_agg.
// ---------------------------------------------------------------------------
__global__ __launch_bounds__(128) void gemm_k(const float* __restrict__ X,
                                              const float* __restrict__ W,
                                              const float* __restrict__ bias) {
    __shared__ float Ws[64][65];
    __shared__ float Xs[32][65];
    int tx = threadIdx.x;
    int row0 = blockIdx.x * 32;
    const float* __restrict__ src = X ? X : (const float*)g_agg;

    for (int i = tx; i < 64 * 16; i += 128) {
        int k = i >> 4, c4 = (i & 15) * 4;
        float4 v = *(const float4*)(W + k * 64 + c4);
        Ws[k][c4] = v.x; Ws[k][c4 + 1] = v.y; Ws[k][c4 + 2] = v.z; Ws[k][c4 + 3] = v.w;
    }
    for (int i = tx; i < 32 * 16; i += 128) {
        int r = i >> 4, c4 = (i & 15) * 4;
        int gr = row0 + r;
        float4 v = make_float4(0.f, 0.f, 0.f, 0.f);
        if (gr < NN) v = *(const float4*)(src + (size_t)gr * 64 + c4);
        if (bias) {
            v.x = fmaxf(v.x + bias[c4], 0.f);
            v.y = fmaxf(v.y + bias[c4 + 1], 0.f);
            v.z = fmaxf(v.z + bias[c4 + 2], 0.f);
            v.w = fmaxf(v.w + bias[c4 + 3], 0.f);
        }
        Xs[r][c4] = v.x; Xs[r][c4 + 1] = v.y; Xs[r][c4 + 2] = v.z; Xs[r][c4 + 3] = v.w;
    }
    __syncthreads();

    int rB = (tx >> 4) * 4;   // 0..28
    int cB = (tx & 15) * 4;   // 0..60
    float acc[4][4] = {};
#pragma unroll
    for (int k = 0; k < 64; k++) {
        float xv[4], wv[4];
#pragma unroll
        for (int i = 0; i < 4; i++) xv[i] = Xs[rB + i][k];
#pragma unroll
        for (int j = 0; j < 4; j++) wv[j] = Ws[k][cB + j];
#pragma unroll
        for (int i = 0; i < 4; i++)
#pragma unroll
            for (int j = 0; j < 4; j++) acc[i][j] = fmaf(xv[i], wv[j], acc[i][j]);
    }
#pragma unroll
    for (int i = 0; i < 4; i++) {
        int gr = row0 + rB + i;
        if (gr < NN) {
            __half2 h01 = __floats2half2_rn(acc[i][0], acc[i][1]);
            __half2 h23 = __floats2half2_rn(acc[i][2], acc[i][3]);
            uint2 pv;
            pv.x = *reinterpret_cast<unsigned*>(&h01);
            pv.y = *reinterpret_cast<unsigned*>(&h23);
            *(uint2*)(g_h + (size_t)gr * 64 + cB) = pv;
        }
    }
}

// ---------------------------------------------------------------------------
// Gather: warp per node, 2 dims per lane (half2 loads), unroll-4 for MLP,
// packed edge stream. Accumulation in fp32.
// ---------------------------------------------------------------------------
__device__ __forceinline__ float2 gather_row(int node, int lane) {
    int beg = g_off[node];
    int end = g_off[node + 1];
    float s = g_dis[node];
    float self = 2.0f * s * s;
    float2 h0 = __half22float2(*(const __half2*)(g_h + (size_t)node * 64 + lane * 2));
    float ax = h0.x * self, ay = h0.y * self;

    int j = beg;
    for (; j + 3 < end; j += 4) {
        int2 p0 = g_edge[j];
        int2 p1 = g_edge[j + 1];
        int2 p2 = g_edge[j + 2];
        int2 p3 = g_edge[j + 3];
        float2 v0 = __half22float2(*(const __half2*)(g_h + (size_t)p0.x * 64 + lane * 2));
        float2 v1 = __half22float2(*(const __half2*)(g_h + (size_t)p1.x * 64 + lane * 2));
        float2 v2 = __half22float2(*(const __half2*)(g_h + (size_t)p2.x * 64 + lane * 2));
        float2 v3 = __half22float2(*(const __half2*)(g_h + (size_t)p3.x * 64 + lane * 2));
        float w0 = __int_as_float(p0.y), w1 = __int_as_float(p1.y);
        float w2 = __int_as_float(p2.y), w3 = __int_as_float(p3.y);
        ax = fmaf(w0, v0.x, ax); ay = fmaf(w0, v0.y, ay);
        ax = fmaf(w1, v1.x, ax); ay = fmaf(w1, v1.y, ay);
        ax = fmaf(w2, v2.x, ax); ay = fmaf(w2, v2.y, ay);
        ax = fmaf(w3, v3.x, ax); ay = fmaf(w3, v3.y, ay);
    }
    for (; j < end; j++) {
        int2 p0 = g_edge[j];
        float w0 = __int_as_float(p0.y);
        float2 v0 = __half22float2(*(const __half2*)(g_h + (size_t)p0.x * 64 + lane * 2));
        ax = fmaf(w0, v0.x, ax); ay = fmaf(w0, v0.y, ay);
    }
    return make_float2(ax, ay);
}

__global__ __launch_bounds__(256) void gather_k() {
    int warp = (blockIdx.x * blockDim.x + threadIdx.x) >> 5;
    int lane = threadIdx.x & 31;
    if (warp >= NN) return;
    float2 acc = gather_row(warp, lane);
    *(float2*)(g_agg + (size_t)warp * 64 + lane * 2) = acc;
}

// Last layer: gather fused with relu(agg+b).Wf + bf -> out
__global__ __launch_bounds__(256) void gather_final_k(const float* __restrict__ bias,
                                                      const float* __restrict__ Wf,
                                                      const float* __restrict__ bf,
                                                      float* __restrict__ out) {
    int warp = (blockIdx.x * blockDim.x + threadIdx.x) >> 5;
    int lane = threadIdx.x & 31;
    if (warp >= NN) return;
    float2 acc = gather_row(warp, lane);
    float s = fmaxf(acc.x + bias[lane * 2], 0.f) * Wf[lane * 2]
            + fmaxf(acc.y + bias[lane * 2 + 1], 0.f) * Wf[lane * 2 + 1];
#pragma unroll
    for (int o = 16; o; o >>= 1) s += __shfl_xor_sync(0xFFFFFFFFu, s, o);
    if (lane == 0) out[warp] = s + bf[0];
}

// ---------------------------------------------------------------------------
extern "C" void kernel_launch(void* const* d_in, const int* in_sizes, int n_in,
                              void* d_out, int out_size) {
    const float* x   = (const float*)d_in[0];
    const int*   ei  = (const int*)d_in[1];    // [2, E] int32
    const float* ew  = (const float*)d_in[2];
    const float* Ws  = (const float*)d_in[3];  // [3, 64, 64]
    const float* bs  = (const float*)d_in[4];  // [3, 64]
    const float* Wf  = (const float*)d_in[5];  // [64, 1]
    const float* bf  = (const float*)d_in[6];
    float*       out = (float*)d_out;

    const int* rows = ei;        // source nodes
    const int* cols = ei + EE;   // target nodes

    const int TB = 256;
    const int gemm_blocks = (NN + 31) / 32;
    const int node_warp_blocks = (NN * 32 + TB - 1) / TB;
    const int edge_blocks = (EE + TB - 1) / TB;

    // --- CSR build + gcn_norm (once; reused across layers) ---
    init_k<<<(NN + TB - 1) / TB, TB>>>();
    count_k<<<edge_blocks, TB>>>(cols, ew);
    scan_k<<<1, 1024>>>();
    rsqrt_k<<<(NN + TB - 1) / TB, TB>>>();
    fill_k<<<edge_blocks, TB>>>(rows, cols, ew);

    // --- layer 0 ---
    gemm_k<<<gemm_blocks, 128>>>(x, Ws, nullptr);
    gather_k<<<node_warp_blocks, TB>>>();

    // --- layer 1 (bias0+relu fused into GEMM read of g_agg) ---
    gemm_k<<<gemm_blocks, 128>>>(nullptr, Ws + 64 * 64, bs);
    gather_k<<<node_warp_blocks, TB>>>();

    // --- layer 2 + final projection fused into the gather ---
    gemm_k<<<gemm_blocks, 128>>>(nullptr, Ws + 2 * 64 * 64, bs + 64);
    gather_final_k<<<node_warp_blocks, TB>>>(bs + 128, Wf, bf, out);
}